// round 12
// baseline (speedup 1.0000x reference)
#include <cuda_runtime.h>
#include <cstdint>

// DotProductCostVolume via mma.sync tf32 band-GEMM (sm_80+ path — compiles for
// plain compute_103; tcgen05 is unavailable under the harness's flags).
// out[b,d,h,w] = (1/32) * sum_c L[b,c,h,w]*R[b,c,h,w-d], 0 if w<d.
// B=4, C=32, H=256, W=512, D=64, fp32.
//
// Per CTA (b, h, 128-wide w tile), 256 threads / 8 warps:
//   A[m][c] = L[c, w0+m]        (M=128, K=32)
//   B[n][c] = R[c, w0-64+n]     (N=192, zero for w0-64+n<0 via cp.async zfill)
//   warp wd computes the diagonal band strip D[16wd..+16, 16wd..+80) with
//   10 x 4 = 40 mma.m16n8k8.tf32 -> out[d, w0+m] = D[m][m+64-d]/32.
// Staging writes straight into FRAGMENT-MAJOR smem slots (cp.async 4B scatter,
// global-coalesced reads), so fragment loads are conflict-free LDS.128/LDS.64.
// Epilogue: frag -> T[d][m] (pitch 132, conflict-free STS) -> coalesced __stcs.

#define Bn 4
#define Cn 32
#define Hn 256
#define Wn 512
#define Dn 64
#define TW 128
#define NB 192
#define NT 256
#define HW (Hn*Wn)
#define BFW 4096        // BF starts at float index 4096 (16KB)
#define TPITCH 132

__device__ __forceinline__ void cp4(uint32_t s, const void* g, bool v) {
    asm volatile("cp.async.ca.shared.global [%0], [%1], 4, %2;"
                 :: "r"(s), "l"(g), "r"(v ? 4u : 0u));
}
__device__ __forceinline__ uint32_t f2tf(float f) {
    uint32_t r;
    asm("cvt.rna.tf32.f32 %0, %1;" : "=r"(r) : "f"(f));
    return r;
}

__global__ __launch_bounds__(NT, 2)
void cost_volume_kernel(const float* __restrict__ left,
                        const float* __restrict__ right,
                        float* __restrict__ out)
{
    // 40KB: AF[0,4096) + BF[4096,10240) floats; reused as T[64][132] (33.8KB).
    __shared__ __align__(16) float smem[10240];

    const int tile = blockIdx.x;    // 0..3
    const int h    = blockIdx.y;    // 0..255
    const int b    = blockIdx.z;    // 0..3
    const int w0   = tile * TW;
    const int tid  = threadIdx.x;
    const int lane = tid & 31;
    const int wd   = tid >> 5;      // warp 0..7

    const float* lbase = left  + (long)(b * Cn) * HW + (long)h * Wn;
    const float* rbase = right + (long)(b * Cn) * HW + (long)h * Wn;
    const uint32_t sbase = (uint32_t)__cvta_generic_to_shared(smem);

    // ---- Stage A into fragment-major slots ----
    // m16n8k8.tf32 A-frag: a0:(g,tig) a1:(g+8,tig) a2:(g,tig+4) a3:(g+8,tig+4)
    // AF float off = (mt*4+ks)*128 + (4g+tig)*4 + (rm + 2*rc)
    #pragma unroll
    for (int it = 0; it < 16; it++) {
        int idx = it * NT + tid;       // [0,4096)
        int m = idx & 127, c = idx >> 7;
        int g = m & 7, rm = (m >> 3) & 1, mt = m >> 4;
        int ks = c >> 3, cc = c & 7, tig = cc & 3, rc = cc >> 2;
        int off = (mt * 4 + ks) * 128 + (4 * g + tig) * 4 + rm + 2 * rc;
        cp4(sbase + 4u * (uint32_t)off, lbase + (long)c * HW + w0 + m, true);
    }
    // ---- Stage B (with zfill halo) into fragment-major slots ----
    // B-frag: b0:(k=tig, n=g) b1:(k=tig+4, n=g)
    // BF float off = BFW + (nt*4+ks)*64 + (4g+tig)*2 + rb
    #pragma unroll
    for (int it = 0; it < 24; it++) {
        int idx = it * NT + tid;       // [0,6144)
        int c = idx / NB, n = idx - c * NB;
        int g = n & 7, nt = n >> 3;
        int ks = c >> 3, cc = c & 7, tig = cc & 3, rb = cc >> 2;
        int off = BFW + (nt * 4 + ks) * 64 + (4 * g + tig) * 2 + rb;
        int wq = w0 - 64 + n;
        bool v = (wq >= 0);
        cp4(sbase + 4u * (uint32_t)off, rbase + (long)c * HW + (v ? wq : 0), v);
    }
    asm volatile("cp.async.commit_group;");
    asm volatile("cp.async.wait_group 0;");
    __syncthreads();

    // ---- Band MMA: warp wd -> D strip [16wd, 16wd+16) x [16wd, 16wd+80) ----
    float dacc[10][4];
    #pragma unroll
    for (int u = 0; u < 10; u++)
        #pragma unroll
        for (int r = 0; r < 4; r++)
            dacc[u][r] = 0.0f;

    #pragma unroll
    for (int ks = 0; ks < 4; ks++) {
        float4 av = *(const float4*)(smem + (wd * 4 + ks) * 128 + lane * 4);
        uint32_t a0 = f2tf(av.x), a1 = f2tf(av.y),
                 a2 = f2tf(av.z), a3 = f2tf(av.w);
        #pragma unroll
        for (int u = 0; u < 10; u++) {
            int nt = 2 * wd + u;
            float2 bv = *(const float2*)(smem + BFW + (nt * 4 + ks) * 64 + lane * 2);
            uint32_t b0 = f2tf(bv.x), b1 = f2tf(bv.y);
            asm("mma.sync.aligned.m16n8k8.row.col.f32.tf32.tf32.f32 "
                "{%0,%1,%2,%3}, {%4,%5,%6,%7}, {%8,%9}, {%0,%1,%2,%3};"
                : "+f"(dacc[u][0]), "+f"(dacc[u][1]),
                  "+f"(dacc[u][2]), "+f"(dacc[u][3])
                : "r"(a0), "r"(a1), "r"(a2), "r"(a3), "r"(b0), "r"(b1));
        }
    }
    __syncthreads();   // all fragment reads done; smem becomes T[64][132]

    // ---- Fragment -> T[d][m] diagonal scatter (conflict-free STS) ----
    {
        const int m0 = 16 * wd;
        const int gr = lane >> 2, tg = lane & 3;
        #pragma unroll
        for (int u = 0; u < 10; u++) {
            int nbase = (2 * wd + u) * 8 + 2 * tg;
            #pragma unroll
            for (int r = 0; r < 4; r++) {
                int m = m0 + gr + 8 * (r >> 1);
                int n = nbase + (r & 1);
                int d = m + 64 - n;
                if (d >= 0 && d < Dn)
                    smem[d * TPITCH + m] = dacc[u][r] * 0.03125f;
            }
        }
    }
    __syncthreads();

    // ---- T -> global, coalesced streaming stores ----
    // thread (dd = tid>>2, wq = tid&3): float4s at w = 4wq + 16k, k=0..7
    {
        const int dd = tid >> 2;
        const int wq = tid & 3;
        const float* rowp = smem + dd * TPITCH + 4 * wq;
        float* op = out + ((long)(b * Dn + dd) * Hn + h) * Wn + w0 + 4 * wq;
        #pragma unroll
        for (int k = 0; k < 8; k++) {
            float4 v = *(const float4*)(rowp + 16 * k);
            __stcs((float4*)(op + 16 * k), v);
        }
    }
}

extern "C" void kernel_launch(void* const* d_in, const int* in_sizes, int n_in,
                              void* d_out, int out_size)
{
    const float* left  = (const float*)d_in[0];
    const float* right = (const float*)d_in[1];
    float* out = (float*)d_out;

    dim3 grid(Wn / TW, Hn, Bn);   // (4, 256, 4) = 4096 CTAs
    cost_volume_kernel<<<grid, NT>>>(left, right, out);
}

// round 13
// speedup vs baseline: 1.5925x; 1.5925x over previous
#include <cuda_runtime.h>
#include <cstdint>

// DotProductCostVolume via mma.sync tf32 band-GEMM, natural-layout staging.
// out[b,d,h,w] = (1/32) * sum_c L[b,c,h,w]*R[b,c,h,w-d], 0 if w<d.
// B=4, C=32, H=256, W=512, D=64, fp32.
//
// Per CTA (b, h, 128-wide w tile), 256 threads / 8 warps:
//   Ls[c][m] = L[c, w0+m]      pitch 136 floats (136 mod 32 = 8)
//   Rs[c][n] = R[c, w0-64+n]   pitch 200 floats (200 mod 32 = 8), zfill halo
// Staged with plain coalesced cp.async.16 (cheap). mma fragments are loaded
// straight from the natural layout with scalar LDS.32 — the pitch-mod-8 trick
// makes the 32 lane addresses hit 32 distinct banks (conflict-free, no repack).
// Warp wd computes band strip D[16wd..+16) x [16wd..+80) with 40 m16n8k8 tf32
// mmas; out[d, w0+m] = D[m][m+64-d]/32 (halo zeros give the w<d mask).
// Epilogue: frag -> T[64][132] diagonal scatter -> coalesced __stcs.

#define Bn 4
#define Cn 32
#define Hn 256
#define Wn 512
#define Dn 64
#define TW 128
#define NB 192
#define NT 256
#define HW (Hn*Wn)
#define PL 136          // Ls pitch (floats)
#define PR 200          // Rs pitch (floats)
#define RS_OFF (Cn*PL)  // Rs starts at float 4352
#define TPITCH 132

__device__ __forceinline__ void cp16(uint32_t s, const void* g, bool v) {
    asm volatile("cp.async.ca.shared.global [%0], [%1], 16, %2;"
                 :: "r"(s), "l"(g), "r"(v ? 16u : 0u));
}
__device__ __forceinline__ uint32_t f2tf(float f) {
    uint32_t r;
    asm("cvt.rna.tf32.f32 %0, %1;" : "=r"(r) : "f"(f));
    return r;
}

__global__ __launch_bounds__(NT, 2)
void cost_volume_kernel(const float* __restrict__ left,
                        const float* __restrict__ right,
                        float* __restrict__ out)
{
    // Ls 4352 + Rs 6400 = 10752 floats (42KB); reused as T[64][132] (33.8KB).
    __shared__ __align__(16) float smem[Cn * PL + Cn * PR];

    const int tile = blockIdx.x;    // 0..3
    const int h    = blockIdx.y;    // 0..255
    const int b    = blockIdx.z;    // 0..3
    const int w0   = tile * TW;
    const int tid  = threadIdx.x;
    const int lane = tid & 31;
    const int wd   = tid >> 5;      // warp 0..7

    const float* lbase = left  + (long)(b * Cn) * HW + (long)h * Wn;
    const float* rbase = right + (long)(b * Cn) * HW + (long)h * Wn;
    const uint32_t sbase = (uint32_t)__cvta_generic_to_shared(smem);

    // ---- Stage Ls: 32 rows x 128 floats = 1024 cp16 (4/thread) ----
    #pragma unroll
    for (int it = 0; it < 4; it++) {
        int idx = it * NT + tid;        // [0,1024)
        int c = idx >> 5, q = idx & 31;
        cp16(sbase + 4u * (uint32_t)(c * PL + 4 * q),
             lbase + (long)c * HW + w0 + 4 * q, true);
    }
    // ---- Stage Rs: 32 rows x 192 floats = 1536 cp16 (6/thread), zfill halo ----
    #pragma unroll
    for (int it = 0; it < 6; it++) {
        int idx = it * NT + tid;        // [0,1536)
        int c = idx / 48, q = idx - c * 48;
        int gw = w0 - 64 + 4 * q;       // chunk entirely <0 or >=0
        bool v = (gw >= 0);
        cp16(sbase + 4u * (uint32_t)(RS_OFF + c * PR + 4 * q),
             rbase + (long)c * HW + (v ? gw : 0), v);
    }
    asm volatile("cp.async.commit_group;");
    asm volatile("cp.async.wait_group 0;");
    __syncthreads();

    // ---- Band MMA: warp wd -> D strip [16wd,16wd+16) x [16wd,16wd+80) ----
    const int g  = lane >> 2;           // fragment group row 0..7
    const int tg = lane & 3;            // thread-in-group 0..3
    const int m0 = 16 * wd;

    float dacc[10][4];
    #pragma unroll
    for (int u = 0; u < 10; u++)
        #pragma unroll
        for (int r = 0; r < 4; r++)
            dacc[u][r] = 0.0f;

    #pragma unroll
    for (int ks = 0; ks < 4; ks++) {
        const int c8 = ks * 8;
        // A fragment (row-major m16k8): a0=(g,tg) a1=(g+8,tg) a2=(g,tg+4) a3=(g+8,tg+4)
        const float* Ar0 = smem + (c8 + tg) * PL + m0 + g;       // row c8+tg
        const float* Ar1 = smem + (c8 + tg + 4) * PL + m0 + g;   // row c8+tg+4
        uint32_t a0 = f2tf(Ar0[0]), a1 = f2tf(Ar0[8]);
        uint32_t a2 = f2tf(Ar1[0]), a3 = f2tf(Ar1[8]);
        #pragma unroll
        for (int u = 0; u < 10; u++) {
            const int n0 = m0 + 8 * u;
            // B fragment (col-major k8n8): b0=(k=tg, n=g) b1=(k=tg+4, n=g)
            uint32_t b0 = f2tf(smem[RS_OFF + (c8 + tg) * PR + n0 + g]);
            uint32_t b1 = f2tf(smem[RS_OFF + (c8 + tg + 4) * PR + n0 + g]);
            asm("mma.sync.aligned.m16n8k8.row.col.f32.tf32.tf32.f32 "
                "{%0,%1,%2,%3}, {%4,%5,%6,%7}, {%8,%9}, {%0,%1,%2,%3};"
                : "+f"(dacc[u][0]), "+f"(dacc[u][1]),
                  "+f"(dacc[u][2]), "+f"(dacc[u][3])
                : "r"(a0), "r"(a1), "r"(a2), "r"(a3), "r"(b0), "r"(b1));
        }
    }
    __syncthreads();   // all smem reads done; smem becomes T[64][132]

    // ---- Fragment -> T[d][m] diagonal scatter ----
    // dacc[u]: d0=(m0+g, n0+2tg) d1=(.., n0+2tg+1) d2=(m0+g+8, n0+2tg) d3=(..+1)
    #pragma unroll
    for (int u = 0; u < 10; u++) {
        int nbase = m0 + 8 * u + 2 * tg;
        #pragma unroll
        for (int r = 0; r < 4; r++) {
            int m = m0 + g + 8 * (r >> 1);
            int n = nbase + (r & 1);
            int d = m + 64 - n;
            if (d >= 0 && d < Dn)
                smem[d * TPITCH + m] = dacc[u][r] * 0.03125f;
        }
    }
    __syncthreads();

    // ---- T -> global, coalesced streaming stores ----
    {
        const int dd = tid >> 2;        // d 0..63
        const int wq = tid & 3;
        const float* rowp = smem + dd * TPITCH + 4 * wq;
        float* op = out + ((long)(b * Dn + dd) * Hn + h) * Wn + w0 + 4 * wq;
        #pragma unroll
        for (int k = 0; k < 8; k++) {
            float4 v = *(const float4*)(rowp + 16 * k);
            __stcs((float4*)(op + 16 * k), v);
        }
    }
}

extern "C" void kernel_launch(void* const* d_in, const int* in_sizes, int n_in,
                              void* d_out, int out_size)
{
    const float* left  = (const float*)d_in[0];
    const float* right = (const float*)d_in[1];
    float* out = (float*)d_out;

    dim3 grid(Wn / TW, Hn, Bn);   // (4, 256, 4) = 4096 CTAs
    cost_volume_kernel<<<grid, NT>>>(left, right, out);
}